// round 14
// baseline (speedup 1.0000x reference)
#include <cuda_runtime.h>
#include <math.h>
#include <stdint.h>

#define BSZ   1024
#define NP    256
#define DIM   128
#define TB    51200      // triplets per batch segment (T1 == T3)
#define TL    12800      // triplets per lca segment   (T2 == T4)
#define TTOT  (2*TB + 2*TL)
#define NGBLK (TTOT / 8)
#define LPAD  129        // smem row stride (conflict-free for c-consecutive access)

// ---------------- scratch (static device globals; no allocation) ------------
__device__ float  g_Dz[BSZ * NP];    // dist(z_s, lh)
__device__ float  g_Dt[BSZ * NP];    // dist(t_s, lh)
__device__ float  g_Dll[NP * NP];    // dist(lh, lh)

// monotone float->u32 map (order-preserving, injective) and its inverse
__device__ __forceinline__ unsigned ordu(float f) {
    int b = __float_as_int(f);
    return (unsigned)(b ^ ((b >> 31) | 0x80000000));
}
__device__ __forceinline__ float iordu(unsigned u) {
    unsigned b = (u & 0x80000000u) ? (u ^ 0x80000000u) : ~u;
    return __int_as_float((int)b);
}

// 256-bit streaming load: no L1 allocation, L2 evict-first (zero-reuse gumbel).
// sm_103 requires 256-bit width (.v4.b64) for this modifier combination.
__device__ __forceinline__ void ldg_stream8(const float* p, float* v) {
    unsigned long long q0, q1, q2, q3;
    asm("ld.global.L1::no_allocate.L2::evict_first.v4.b64 {%0,%1,%2,%3}, [%4];"
        : "=l"(q0), "=l"(q1), "=l"(q2), "=l"(q3) : "l"(p));
    v[0] = __uint_as_float((unsigned)q0);  v[1] = __uint_as_float((unsigned)(q0 >> 32));
    v[2] = __uint_as_float((unsigned)q1);  v[3] = __uint_as_float((unsigned)(q1 >> 32));
    v[4] = __uint_as_float((unsigned)q2);  v[5] = __uint_as_float((unsigned)(q2 >> 32));
    v[6] = __uint_as_float((unsigned)q3);  v[7] = __uint_as_float((unsigned)(q3 >> 32));
}

// poincare composite scale + final squared norm, from the raw row norm^2
__device__ __forceinline__ void poinc_scales(float sum0, float& alpha, float& y2) {
    const float sqrt_c = 0.31622776601683794f;       // sqrt(0.1)
    const float maxn   = (1.0f - 1e-3f) / 0.31622776601683794f;
    float n0 = sqrtf(sum0);
    float s1 = fminf(1.0f, 2.3f / (n0 + 1e-5f));     // clip to radius 2.3
    float n1 = fmaxf(n0 * s1, 1e-5f);
    float arg = sqrt_c * n1;
    float s2 = tanhf(arg) / arg;                     // expmap0
    float n2 = fmaxf(n1 * s2, 1e-5f);
    float s3 = (n2 > maxn) ? (maxn / n2) : 1.0f;     // project
    float n3 = n2 * s3;
    alpha = s1 * s2 * s3;
    y2    = n3 * n3;
}

// ---------------- self-contained distance matrices ---------------------------
// lh = alpha ⊙ lcas (per-row scalar), computed in-block from raw lcas tiles.
// grid 288 = 72 row-segments (32 z, 32 t, 8 lh of 32 rows) x 4 col tiles.
__global__ __launch_bounds__(256) void k_dist_all(const float* __restrict__ lcas,
                                                  const float* __restrict__ z,
                                                  const float* __restrict__ t,
                                                  float* __restrict__ outp) {
    __shared__ float ls[64 * LPAD];   // column tile: 64 lcas rows (scaled to lh)
    __shared__ float xs[32 * LPAD];   // X tile: 32 source rows
    __shared__ float y2c[64];         // ||lh_col||^2
    __shared__ float x2r[32];         // ||x_row||^2 (post-scale for lh rows)

    const int b    = blockIdx.x;
    const int tid  = threadIdx.x;
    const int warp = tid >> 5, lane = tid & 31;

    if (b == 0 && tid == 0) outp[0] = 0.0f;          // zero loss accumulator

    const int ct = b & 3;            // column tile 0..3
    const int rb = b >> 2;           // row segment 0..71
    const int c0 = ct * 64;

    const float* __restrict__ X;
    float* __restrict__ out;
    int r0; bool x_is_lh;
    if (rb < 32)      { X = z;    out = g_Dz;  r0 = rb * 32;        x_is_lh = false; }
    else if (rb < 64) { X = t;    out = g_Dt;  r0 = (rb - 32) * 32; x_is_lh = false; }
    else              { X = lcas; out = g_Dll; r0 = (rb - 64) * 32; x_is_lh = true;  }

    // ---- load tiles (coalesced global reads) ----
    #pragma unroll
    for (int idx = tid; idx < 64 * DIM; idx += 256) {
        int r = idx >> 7, d = idx & 127;
        ls[r * LPAD + d] = lcas[(c0 + r) * DIM + d];
    }
    #pragma unroll
    for (int idx = tid; idx < 32 * DIM; idx += 256) {
        int r = idx >> 7, d = idx & 127;
        xs[r * LPAD + d] = X[(r0 + r) * DIM + d];
    }
    __syncthreads();

    // ---- poincare-scale the column tile: warp w handles cols w*8..w*8+7 ----
    #pragma unroll
    for (int cc = 0; cc < 8; ++cc) {
        const int col = warp * 8 + cc;
        float v[4], s = 0.0f;
        #pragma unroll
        for (int q = 0; q < 4; ++q) {
            v[q] = ls[col * LPAD + lane + 32 * q];
            s = fmaf(v[q], v[q], s);
        }
        #pragma unroll
        for (int off = 16; off > 0; off >>= 1) s += __shfl_xor_sync(0xffffffffu, s, off);
        float alpha, y2; poinc_scales(s, alpha, y2);
        #pragma unroll
        for (int q = 0; q < 4; ++q) ls[col * LPAD + lane + 32 * q] = v[q] * alpha;
        if (lane == 0) y2c[col] = y2;
    }
    // ---- X rows: warp w handles rows w*4..w*4+3 ----
    #pragma unroll
    for (int rr = 0; rr < 4; ++rr) {
        const int row = warp * 4 + rr;
        float v[4], s = 0.0f;
        #pragma unroll
        for (int q = 0; q < 4; ++q) {
            v[q] = xs[row * LPAD + lane + 32 * q];
            s = fmaf(v[q], v[q], s);
        }
        #pragma unroll
        for (int off = 16; off > 0; off >>= 1) s += __shfl_xor_sync(0xffffffffu, s, off);
        if (x_is_lh) {
            float alpha, y2; poinc_scales(s, alpha, y2);
            #pragma unroll
            for (int q = 0; q < 4; ++q) xs[row * LPAD + lane + 32 * q] = v[q] * alpha;
            if (lane == 0) x2r[row] = y2;
        } else {
            if (lane == 0) x2r[row] = s;
        }
    }
    __syncthreads();

    // ---- dot products: thread = (col c = tid&63, row group rg = tid>>6) ----
    const int c  = tid & 63;
    const int rg = tid >> 6;          // 0..3, 8 rows each
    float acc[8] = {0,0,0,0,0,0,0,0};
    #pragma unroll 4
    for (int d = 0; d < DIM; ++d) {
        float lv = ls[c * LPAD + d];
        #pragma unroll
        for (int q = 0; q < 8; ++q)
            acc[q] = fmaf(xs[(rg * 8 + q) * LPAD + d], lv, acc[q]);
    }

    // ---- hyperbolic distance epilogue + store ----
    const float y2 = y2c[c];
    const float cc_ = 0.1f;
    #pragma unroll
    for (int q = 0; q < 8; ++q) {
        const int row = rg * 8 + q;
        float x2    = x2r[row];
        float xy    = -acc[q];                               // (-x).y
        float a     = 1.0f + 2.0f * cc_ * xy + cc_ * y2;
        float bb    = 1.0f - cc_ * x2;
        float denom = 1.0f + 2.0f * cc_ * xy + (cc_ * cc_) * x2 * y2;
        float numsq = a * a * x2 + 2.0f * a * bb * xy + bb * bb * y2;
        float nrm   = sqrtf(fmaxf(numsq, 1e-12f)) / fabsf(denom + 1e-5f);
        float v = 0.31622776601683794f * nrm;
        v = fminf(fmaxf(v, -0.99999f), 0.99999f);
        float art = 0.5f * (log1pf(v) - log1pf(-v));
        out[(r0 + row) * NP + (c0 + c)] = 6.324555320336759f * art;
    }
}

// ---------------- fused ghhc over all 4 triplet sets -------------------------
// One warp per triplet; lane owns 8 contiguous proxies. Phase-split (small live
// set). Round-11 body, but 6 blocks/SM (42-reg target) for more warps in flight.
__global__ __launch_bounds__(256, 6) void k_ghhc_all(
    const int*  __restrict__ t1, const int*  __restrict__ t2,
    const int*  __restrict__ t3, const int*  __restrict__ t4,
    const float* __restrict__ G1, const float* __restrict__ G2,
    const float* __restrict__ G3, const float* __restrict__ G4,
    float* __restrict__ outp) {
    __shared__ float wsum[8];
    const int warp = threadIdx.x >> 5;
    const int lane = threadIdx.x & 31;
    const int w    = blockIdx.x * 8 + warp;

    const int* trip; const float* g; const float* D; int T, t; float invT;
    if (w < TB)                { trip = t1; g = G1; D = g_Dz;  T = TB; t = w;                 invT = 1.0f / TB; }
    else if (w < TB + TL)      { trip = t2; g = G2; D = g_Dll; T = TL; t = w - TB;            invT = 1.0f / TL; }
    else if (w < 2*TB + TL)    { trip = t3; g = G3; D = g_Dt;  T = TB; t = w - (TB + TL);     invT = 1.0f / TB; }
    else                       { trip = t4; g = G4; D = g_Dll; T = TL; t = w - (2*TB + TL);   invT = 1.0f / TL; }

    const int i = trip[t];
    const int j = trip[T + t];
    const int k = trip[2 * T + t];
    const float* __restrict__ di = D + (size_t)i * NP;
    const float* __restrict__ dj = D + (size_t)j * NP;
    const float* __restrict__ dk = D + (size_t)k * NP;
    const float* __restrict__ g0 = g + (size_t)t * NP;
    const float* __restrict__ g1 = g + ((size_t)T + t) * NP;
    const int base = lane * 8;

    float m[8];
    int idx0, idx1;

    // ---- phase A: di, dj, g0 -> max_ij, argmax0 ----
    {
        float4 a0 = *(const float4*)(di + base), a1 = *(const float4*)(di + base + 4);
        float4 b0 = *(const float4*)(dj + base), b1 = *(const float4*)(dj + base + 4);
        float ev[8];
        ldg_stream8(g0 + base, ev);
        float av[8] = {a0.x, a0.y, a0.z, a0.w, a1.x, a1.y, a1.z, a1.w};
        float bv[8] = {b0.x, b0.y, b0.z, b0.w, b1.x, b1.y, b1.z, b1.w};
        float s0[8], lmax = -INFINITY;
        #pragma unroll
        for (int u = 0; u < 8; ++u) {
            m[u]  = fmaxf(av[u], bv[u]);
            s0[u] = fmaf(m[u], -10.0f, ev[u]);        // g - max/tau
            lmax  = fmaxf(lmax, s0[u]);
        }
        float wmax = iordu(__reduce_max_sync(0xffffffffu, ordu(lmax)));
        int loc = NP;                                 // sentinel
        #pragma unroll
        for (int u = 7; u >= 0; --u)
            if (s0[u] == wmax) loc = base + u;        // lowest u wins
        unsigned msk = __ballot_sync(0xffffffffu, loc < NP);
        idx0 = __shfl_sync(0xffffffffu, loc, __ffs(msk) - 1);
    }
    // ---- phase B: dk, g1 -> max_ijk, argmax1 ----
    {
        float4 c0 = *(const float4*)(dk + base), c1 = *(const float4*)(dk + base + 4);
        float fv[8];
        ldg_stream8(g1 + base, fv);
        float cv[8] = {c0.x, c0.y, c0.z, c0.w, c1.x, c1.y, c1.z, c1.w};
        float s1[8], lmax = -INFINITY;
        #pragma unroll
        for (int u = 0; u < 8; ++u) {
            float m2 = fmaxf(cv[u], m[u]);
            s1[u] = fmaf(m2, -10.0f, fv[u]);
            lmax  = fmaxf(lmax, s1[u]);
        }
        float wmax = iordu(__reduce_max_sync(0xffffffffu, ordu(lmax)));
        int loc = NP;
        #pragma unroll
        for (int u = 7; u >= 0; --u)
            if (s1[u] == wmax) loc = base + u;
        unsigned msk = __ballot_sync(0xffffffffu, loc < NP);
        idx1 = __shfl_sync(0xffffffffu, loc, __ffs(msk) - 1);
    }

    float hc = 0.0f;
    if (lane == 0 && idx0 != idx1) {                  // diff_lca gate
        float dia = di[idx0], dib = di[idx1];
        float dja = dj[idx0], djb = dj[idx1];
        float dka = dk[idx0], dkb = dk[idx1];
        float h = fmaxf(dia - dib + 0.1f, 0.0f)
                + fmaxf(dja - djb + 0.1f, 0.0f)
                + fmaxf(dkb - dka + 0.1f, 0.0f);
        hc = h * invT;
    }
    if (lane == 0) wsum[warp] = hc;
    __syncthreads();

    if (threadIdx.x == 0) {
        float s = 0.0f;
        #pragma unroll
        for (int q = 0; q < 8; ++q) s += wsum[q];
        atomicAdd(outp, s);                           // fire-and-forget
    }
}

// ---------------- launch -----------------------------------------------------
extern "C" void kernel_launch(void* const* d_in, const int* in_sizes, int n_in,
                              void* d_out, int out_size) {
    const float* z_s   = (const float*)d_in[0];
    const float* t_s   = (const float*)d_in[1];
    /* d_in[2] = y, unused */
    const float* lcas  = (const float*)d_in[3];
    const int*   trip1 = (const int*)d_in[4];
    const int*   trip2 = (const int*)d_in[5];
    const int*   trip3 = (const int*)d_in[6];
    const int*   trip4 = (const int*)d_in[7];
    const float* g1    = (const float*)d_in[8];
    const float* g2    = (const float*)d_in[9];
    const float* g3    = (const float*)d_in[10];
    const float* g4    = (const float*)d_in[11];

    k_dist_all<<<288, 256>>>(lcas, z_s, t_s, (float*)d_out);
    k_ghhc_all<<<NGBLK, 256>>>(trip1, trip2, trip3, trip4,
                               g1, g2, g3, g4, (float*)d_out);
}

// round 15
// speedup vs baseline: 1.0640x; 1.0640x over previous
#include <cuda_runtime.h>
#include <math.h>
#include <stdint.h>

#define BSZ   1024
#define NP    256
#define DIM   128
#define TB    51200      // triplets per batch segment (T1 == T3)
#define TL    12800      // triplets per lca segment   (T2 == T4)
#define TTOT  (2*TB + 2*TL)
#define NGBLK (TTOT / 8)
#define LPAD  132        // smem row stride: 16B-granule stride 33 (conflict-free
                         // for scalar lane-spread AND float4 per-lane access)

// ---------------- scratch (static device globals; no allocation) ------------
__device__ float  g_Dz[BSZ * NP];    // dist(z_s, lh)
__device__ float  g_Dt[BSZ * NP];    // dist(t_s, lh)
__device__ float  g_Dll[NP * NP];    // dist(lh, lh)

// monotone float->u32 map (order-preserving, injective) and its inverse
__device__ __forceinline__ unsigned ordu(float f) {
    int b = __float_as_int(f);
    return (unsigned)(b ^ ((b >> 31) | 0x80000000));
}
__device__ __forceinline__ float iordu(unsigned u) {
    unsigned b = (u & 0x80000000u) ? (u ^ 0x80000000u) : ~u;
    return __int_as_float((int)b);
}

// 256-bit streaming load: no L1 allocation, L2 evict-first (zero-reuse gumbel).
__device__ __forceinline__ void ldg_stream8(const float* p, float* v) {
    unsigned long long q0, q1, q2, q3;
    asm("ld.global.L1::no_allocate.L2::evict_first.v4.b64 {%0,%1,%2,%3}, [%4];"
        : "=l"(q0), "=l"(q1), "=l"(q2), "=l"(q3) : "l"(p));
    v[0] = __uint_as_float((unsigned)q0);  v[1] = __uint_as_float((unsigned)(q0 >> 32));
    v[2] = __uint_as_float((unsigned)q1);  v[3] = __uint_as_float((unsigned)(q1 >> 32));
    v[4] = __uint_as_float((unsigned)q2);  v[5] = __uint_as_float((unsigned)(q2 >> 32));
    v[6] = __uint_as_float((unsigned)q3);  v[7] = __uint_as_float((unsigned)(q3 >> 32));
}

// poincare composite scale + final squared norm, from the raw row norm^2
__device__ __forceinline__ void poinc_scales(float sum0, float& alpha, float& y2) {
    const float sqrt_c = 0.31622776601683794f;       // sqrt(0.1)
    const float maxn   = (1.0f - 1e-3f) / 0.31622776601683794f;
    float n0 = sqrtf(sum0);
    float s1 = fminf(1.0f, 2.3f / (n0 + 1e-5f));     // clip to radius 2.3
    float n1 = fmaxf(n0 * s1, 1e-5f);
    float arg = sqrt_c * n1;
    float s2 = tanhf(arg) / arg;                     // expmap0
    float n2 = fmaxf(n1 * s2, 1e-5f);
    float s3 = (n2 > maxn) ? (maxn / n2) : 1.0f;     // project
    float n3 = n2 * s3;
    alpha = s1 * s2 * s3;
    y2    = n3 * n3;
}

// ---------------- self-contained distance matrices ---------------------------
// lh = alpha ⊙ lcas (per-row scalar), computed in-block from raw lcas tiles.
// grid 288 = 72 row-segments (32 z, 32 t, 8 lh of 32 rows) x 4 col tiles.
// Inner dot loop uses float4 shared loads (LPAD=132 keeps it conflict-free).
__global__ __launch_bounds__(256) void k_dist_all(const float* __restrict__ lcas,
                                                  const float* __restrict__ z,
                                                  const float* __restrict__ t,
                                                  float* __restrict__ outp) {
    __shared__ float ls[64 * LPAD];   // column tile: 64 lcas rows (scaled to lh)
    __shared__ float xs[32 * LPAD];   // X tile: 32 source rows
    __shared__ float y2c[64];         // ||lh_col||^2
    __shared__ float x2r[32];         // ||x_row||^2 (post-scale for lh rows)

    const int b    = blockIdx.x;
    const int tid  = threadIdx.x;
    const int warp = tid >> 5, lane = tid & 31;

    if (b == 0 && tid == 0) outp[0] = 0.0f;          // zero loss accumulator

    const int ct = b & 3;            // column tile 0..3
    const int rb = b >> 2;           // row segment 0..71
    const int c0 = ct * 64;

    const float* __restrict__ X;
    float* __restrict__ out;
    int r0; bool x_is_lh;
    if (rb < 32)      { X = z;    out = g_Dz;  r0 = rb * 32;        x_is_lh = false; }
    else if (rb < 64) { X = t;    out = g_Dt;  r0 = (rb - 32) * 32; x_is_lh = false; }
    else              { X = lcas; out = g_Dll; r0 = (rb - 64) * 32; x_is_lh = true;  }

    // ---- load tiles (coalesced global reads) ----
    #pragma unroll
    for (int idx = tid; idx < 64 * DIM; idx += 256) {
        int r = idx >> 7, d = idx & 127;
        ls[r * LPAD + d] = lcas[(c0 + r) * DIM + d];
    }
    #pragma unroll
    for (int idx = tid; idx < 32 * DIM; idx += 256) {
        int r = idx >> 7, d = idx & 127;
        xs[r * LPAD + d] = X[(r0 + r) * DIM + d];
    }
    __syncthreads();

    // ---- poincare-scale the column tile: warp w handles cols w*8..w*8+7 ----
    #pragma unroll
    for (int cc = 0; cc < 8; ++cc) {
        const int col = warp * 8 + cc;
        float v[4], s = 0.0f;
        #pragma unroll
        for (int q = 0; q < 4; ++q) {
            v[q] = ls[col * LPAD + lane + 32 * q];
            s = fmaf(v[q], v[q], s);
        }
        #pragma unroll
        for (int off = 16; off > 0; off >>= 1) s += __shfl_xor_sync(0xffffffffu, s, off);
        float alpha, y2; poinc_scales(s, alpha, y2);
        #pragma unroll
        for (int q = 0; q < 4; ++q) ls[col * LPAD + lane + 32 * q] = v[q] * alpha;
        if (lane == 0) y2c[col] = y2;
    }
    // ---- X rows: warp w handles rows w*4..w*4+3 ----
    #pragma unroll
    for (int rr = 0; rr < 4; ++rr) {
        const int row = warp * 4 + rr;
        float v[4], s = 0.0f;
        #pragma unroll
        for (int q = 0; q < 4; ++q) {
            v[q] = xs[row * LPAD + lane + 32 * q];
            s = fmaf(v[q], v[q], s);
        }
        #pragma unroll
        for (int off = 16; off > 0; off >>= 1) s += __shfl_xor_sync(0xffffffffu, s, off);
        if (x_is_lh) {
            float alpha, y2; poinc_scales(s, alpha, y2);
            #pragma unroll
            for (int q = 0; q < 4; ++q) xs[row * LPAD + lane + 32 * q] = v[q] * alpha;
            if (lane == 0) x2r[row] = y2;
        } else {
            if (lane == 0) x2r[row] = s;
        }
    }
    __syncthreads();

    // ---- dot products: thread = (col c = tid&63, row group rg = tid>>6) ----
    const int c  = tid & 63;
    const int rg = tid >> 6;          // 0..3, 8 rows each
    float acc[8] = {0,0,0,0,0,0,0,0};
    #pragma unroll 2
    for (int d = 0; d < DIM; d += 4) {
        float4 lv = *(const float4*)&ls[c * LPAD + d];
        #pragma unroll
        for (int q = 0; q < 8; ++q) {
            float4 xv = *(const float4*)&xs[(rg * 8 + q) * LPAD + d];
            acc[q] = fmaf(xv.x, lv.x,
                     fmaf(xv.y, lv.y,
                     fmaf(xv.z, lv.z,
                     fmaf(xv.w, lv.w, acc[q]))));
        }
    }

    // ---- hyperbolic distance epilogue + store ----
    const float y2 = y2c[c];
    const float cc_ = 0.1f;
    #pragma unroll
    for (int q = 0; q < 8; ++q) {
        const int row = rg * 8 + q;
        float x2    = x2r[row];
        float xy    = -acc[q];                               // (-x).y
        float a     = 1.0f + 2.0f * cc_ * xy + cc_ * y2;
        float bb    = 1.0f - cc_ * x2;
        float denom = 1.0f + 2.0f * cc_ * xy + (cc_ * cc_) * x2 * y2;
        float numsq = a * a * x2 + 2.0f * a * bb * xy + bb * bb * y2;
        float nrm   = sqrtf(fmaxf(numsq, 1e-12f)) / fabsf(denom + 1e-5f);
        float v = 0.31622776601683794f * nrm;
        v = fminf(fmaxf(v, -0.99999f), 0.99999f);
        float art = 0.5f * (log1pf(v) - log1pf(-v));
        out[(r0 + row) * NP + (c0 + c)] = 6.324555320336759f * art;
    }
}

// ---------------- fused ghhc over all 4 triplet sets -------------------------
// Byte-exact round-11 body (measured 57.3us): one warp per triplet, phase-split,
// float4 D loads, 256-bit streaming gumbel loads, float-domain argmax with
// REDUX.MAX + ballot, one fire-and-forget atomic per block. (256,5) = 48 regs.
__global__ __launch_bounds__(256, 5) void k_ghhc_all(
    const int*  __restrict__ t1, const int*  __restrict__ t2,
    const int*  __restrict__ t3, const int*  __restrict__ t4,
    const float* __restrict__ G1, const float* __restrict__ G2,
    const float* __restrict__ G3, const float* __restrict__ G4,
    float* __restrict__ outp) {
    __shared__ float wsum[8];
    const int warp = threadIdx.x >> 5;
    const int lane = threadIdx.x & 31;
    const int w    = blockIdx.x * 8 + warp;

    const int* trip; const float* g; const float* D; int T, t; float invT;
    if (w < TB)                { trip = t1; g = G1; D = g_Dz;  T = TB; t = w;                 invT = 1.0f / TB; }
    else if (w < TB + TL)      { trip = t2; g = G2; D = g_Dll; T = TL; t = w - TB;            invT = 1.0f / TL; }
    else if (w < 2*TB + TL)    { trip = t3; g = G3; D = g_Dt;  T = TB; t = w - (TB + TL);     invT = 1.0f / TB; }
    else                       { trip = t4; g = G4; D = g_Dll; T = TL; t = w - (2*TB + TL);   invT = 1.0f / TL; }

    const int i = trip[t];
    const int j = trip[T + t];
    const int k = trip[2 * T + t];
    const float* __restrict__ di = D + (size_t)i * NP;
    const float* __restrict__ dj = D + (size_t)j * NP;
    const float* __restrict__ dk = D + (size_t)k * NP;
    const float* __restrict__ g0 = g + (size_t)t * NP;
    const float* __restrict__ g1 = g + ((size_t)T + t) * NP;
    const int base = lane * 8;

    float m[8];
    int idx0, idx1;

    // ---- phase A: di, dj, g0 -> max_ij, argmax0 ----
    {
        float4 a0 = *(const float4*)(di + base), a1 = *(const float4*)(di + base + 4);
        float4 b0 = *(const float4*)(dj + base), b1 = *(const float4*)(dj + base + 4);
        float ev[8];
        ldg_stream8(g0 + base, ev);
        float av[8] = {a0.x, a0.y, a0.z, a0.w, a1.x, a1.y, a1.z, a1.w};
        float bv[8] = {b0.x, b0.y, b0.z, b0.w, b1.x, b1.y, b1.z, b1.w};
        float s0[8], lmax = -INFINITY;
        #pragma unroll
        for (int u = 0; u < 8; ++u) {
            m[u]  = fmaxf(av[u], bv[u]);
            s0[u] = fmaf(m[u], -10.0f, ev[u]);        // g - max/tau
            lmax  = fmaxf(lmax, s0[u]);
        }
        float wmax = iordu(__reduce_max_sync(0xffffffffu, ordu(lmax)));
        int loc = NP;                                 // sentinel
        #pragma unroll
        for (int u = 7; u >= 0; --u)
            if (s0[u] == wmax) loc = base + u;        // lowest u wins
        unsigned msk = __ballot_sync(0xffffffffu, loc < NP);
        idx0 = __shfl_sync(0xffffffffu, loc, __ffs(msk) - 1);
    }
    // ---- phase B: dk, g1 -> max_ijk, argmax1 ----
    {
        float4 c0 = *(const float4*)(dk + base), c1 = *(const float4*)(dk + base + 4);
        float fv[8];
        ldg_stream8(g1 + base, fv);
        float cv[8] = {c0.x, c0.y, c0.z, c0.w, c1.x, c1.y, c1.z, c1.w};
        float s1[8], lmax = -INFINITY;
        #pragma unroll
        for (int u = 0; u < 8; ++u) {
            float m2 = fmaxf(cv[u], m[u]);
            s1[u] = fmaf(m2, -10.0f, fv[u]);
            lmax  = fmaxf(lmax, s1[u]);
        }
        float wmax = iordu(__reduce_max_sync(0xffffffffu, ordu(lmax)));
        int loc = NP;
        #pragma unroll
        for (int u = 7; u >= 0; --u)
            if (s1[u] == wmax) loc = base + u;
        unsigned msk = __ballot_sync(0xffffffffu, loc < NP);
        idx1 = __shfl_sync(0xffffffffu, loc, __ffs(msk) - 1);
    }

    float hc = 0.0f;
    if (lane == 0 && idx0 != idx1) {                  // diff_lca gate
        float dia = di[idx0], dib = di[idx1];
        float dja = dj[idx0], djb = dj[idx1];
        float dka = dk[idx0], dkb = dk[idx1];
        float h = fmaxf(dia - dib + 0.1f, 0.0f)
                + fmaxf(dja - djb + 0.1f, 0.0f)
                + fmaxf(dkb - dka + 0.1f, 0.0f);
        hc = h * invT;
    }
    if (lane == 0) wsum[warp] = hc;
    __syncthreads();

    if (threadIdx.x == 0) {
        float s = 0.0f;
        #pragma unroll
        for (int q = 0; q < 8; ++q) s += wsum[q];
        atomicAdd(outp, s);                           // fire-and-forget
    }
}

// ---------------- launch -----------------------------------------------------
extern "C" void kernel_launch(void* const* d_in, const int* in_sizes, int n_in,
                              void* d_out, int out_size) {
    const float* z_s   = (const float*)d_in[0];
    const float* t_s   = (const float*)d_in[1];
    /* d_in[2] = y, unused */
    const float* lcas  = (const float*)d_in[3];
    const int*   trip1 = (const int*)d_in[4];
    const int*   trip2 = (const int*)d_in[5];
    const int*   trip3 = (const int*)d_in[6];
    const int*   trip4 = (const int*)d_in[7];
    const float* g1    = (const float*)d_in[8];
    const float* g2    = (const float*)d_in[9];
    const float* g3    = (const float*)d_in[10];
    const float* g4    = (const float*)d_in[11];

    k_dist_all<<<288, 256>>>(lcas, z_s, t_s, (float*)d_out);
    k_ghhc_all<<<NGBLK, 256>>>(trip1, trip2, trip3, trip4,
                               g1, g2, g3, g4, (float*)d_out);
}